// round 5
// baseline (speedup 1.0000x reference)
#include <cuda_runtime.h>
#include <math.h>

#define B_SEQ   2048
#define D_DIM   128
#define H_DIM   128
#define G3      384            // 3*H
#define MAX_LEN 200
#define MAX_T   (B_SEQ * (MAX_LEN - 1))   // 407552 worst-case tokens
#define NSEQ    4              // sequences per GRU block

// Scratch for input projections x @ W_ih^T  : [T, 3H] fp32
__device__ float g_xproj[(size_t)MAX_T * G3];
__device__ int      g_off[B_SEQ];
__device__ unsigned g_order[B_SEQ];   // seq indices sorted by length desc

// packed fp32x2 FMA: d = a*b + d
__device__ __forceinline__ void ffma2(unsigned long long& d,
                                      unsigned long long a,
                                      unsigned long long b) {
    asm volatile("fma.rn.f32x2 %0, %1, %2, %0;" : "+l"(d) : "l"(a), "l"(b));
}
__device__ __forceinline__ float unpack_sum(unsigned long long v) {
    unsigned int lo, hi;
    asm("mov.b64 {%0,%1}, %2;" : "=r"(lo), "=r"(hi) : "l"(v));
    return __uint_as_float(lo) + __uint_as_float(hi);
}

__device__ __forceinline__ float fast_sigmoid(float x) {
    // 1/(1+e^-x); __expf overflow -> inf -> result 0 (correct limit)
    return __fdividef(1.f, 1.f + __expf(-x));
}
__device__ __forceinline__ float fast_tanh(float x) {
    x = fminf(fmaxf(x, -15.f), 15.f);       // avoid inf/inf
    float e2 = __expf(2.f * x);
    return __fdividef(e2 - 1.f, e2 + 1.f);
}

// ---------------------------------------------------------------------------
// Offset normalization (int32 vs int64 input dtype autodetect).
// ---------------------------------------------------------------------------
__global__ void offsets_kernel(const void* __restrict__ off_raw) {
    __shared__ int is64;
    const int* v32 = (const int*)off_raw;
    if (threadIdx.x == 0) {
        int f = 0;
        #pragma unroll
        for (int i = 0; i < 31; ++i) {
            if (v32[i + 1] < v32[i]) f = 1;
        }
        is64 = f;
    }
    __syncthreads();
    int gid = blockIdx.x * blockDim.x + threadIdx.x;
    if (gid < B_SEQ) {
        if (is64) {
            const long long* v64 = (const long long*)off_raw;
            g_off[gid] = (int)v64[gid];
        } else {
            g_off[gid] = v32[gid];
        }
    }
}

// ---------------------------------------------------------------------------
// One-block bitonic sort (length desc, idx) -> equal-length grouping of 4.
// key = (len << 11) | idx
// ---------------------------------------------------------------------------
__global__ void sort_kernel(int T) {
    __shared__ unsigned key[B_SEQ];
    const int tid = threadIdx.x;                 // 1024 threads
    for (int i = tid; i < B_SEQ; i += 1024) {
        int off = g_off[i];
        int end = (i == B_SEQ - 1) ? T : g_off[i + 1];
        key[i] = ((unsigned)(end - off) << 11) | (unsigned)i;
    }
    __syncthreads();
    for (int k = 2; k <= B_SEQ; k <<= 1) {
        for (int s = k >> 1; s > 0; s >>= 1) {
            for (int i = tid; i < B_SEQ; i += 1024) {
                int ixj = i ^ s;
                if (ixj > i) {
                    unsigned a = key[i], b = key[ixj];
                    bool seg_up = ((i & k) == 0);
                    if (seg_up ? (a < b) : (a > b)) { key[i] = b; key[ixj] = a; }
                }
            }
            __syncthreads();
        }
    }
    for (int i = tid; i < B_SEQ; i += 1024) g_order[i] = key[i] & 0x7FFu;
}

// ---------------------------------------------------------------------------
// Kernel 1: persistent x-projection. Grid = 148; weights loaded once/SM.
// ---------------------------------------------------------------------------
#define XTILE 96
__global__ __launch_bounds__(384, 1)
void xproj_kernel(const float* __restrict__ x,
                  const float* __restrict__ W_ih, int T) {
    __shared__ __align__(16) float sx[XTILE * 128];
    const int j = threadIdx.x;

    unsigned long long w2[64];
    {
        const ulonglong2* wr =
            reinterpret_cast<const ulonglong2*>(W_ih + (size_t)j * 128);
        #pragma unroll
        for (int k = 0; k < 32; ++k) {
            ulonglong2 v = wr[k];
            w2[2*k]   = v.x;
            w2[2*k+1] = v.y;
        }
    }

    const int ntiles = (T + XTILE - 1) / XTILE;
    for (int tile = blockIdx.x; tile < ntiles; tile += gridDim.x) {
        const int t0 = tile * XTILE;
        const int ntok = min(XTILE, T - t0);

        __syncthreads();
        const float4* xg = reinterpret_cast<const float4*>(x + (size_t)t0 * D_DIM);
        float4* sx4 = reinterpret_cast<float4*>(sx);
        for (int i = j; i < ntok * 32; i += 384) sx4[i] = xg[i];
        __syncthreads();

        float* outp = g_xproj + (size_t)t0 * G3 + j;
        for (int t = 0; t < ntok; ++t) {
            const ulonglong2* hv =
                reinterpret_cast<const ulonglong2*>(sx + t * D_DIM);
            unsigned long long a0 = 0ull, a1 = 0ull, a2 = 0ull, a3 = 0ull;
            #pragma unroll
            for (int k = 0; k < 16; ++k) {
                ulonglong2 h0 = hv[2*k];
                ulonglong2 h1 = hv[2*k+1];
                ffma2(a0, w2[4*k+0], h0.x);
                ffma2(a1, w2[4*k+1], h0.y);
                ffma2(a2, w2[4*k+2], h1.x);
                ffma2(a3, w2[4*k+3], h1.y);
            }
            outp[(size_t)t * G3] =
                (unpack_sum(a0) + unpack_sum(a1)) + (unpack_sum(a2) + unpack_sum(a3));
        }
    }
}

// ---------------------------------------------------------------------------
// Kernel 2: ragged GRU recurrence, 4 sequences per block (grouped by length).
// Same W_hh registers serve all four dots; fast MUFU-based gates.
// ---------------------------------------------------------------------------
__global__ __launch_bounds__(384, 1)
void gru_kernel(const float* __restrict__ W_hh,
                const float* __restrict__ W_dense,
                const float* __restrict__ b_dense,
                float* __restrict__ out, int T) {
    const int j = threadIdx.x;

    __shared__ __align__(16) float sh_h[NSEQ][128];
    __shared__ float sh_a[NSEQ][384];
    __shared__ float sh_hgn[NSEQ][128];
    __shared__ float sh_red[NSEQ][4];
    __shared__ float sh_inv[NSEQ];
    __shared__ int   sh_meta[NSEQ * 3];       // off, len, sidx

    unsigned long long w2[64];
    {
        const ulonglong2* wr =
            reinterpret_cast<const ulonglong2*>(W_hh + (size_t)j * 128);
        #pragma unroll
        for (int k = 0; k < 32; ++k) {
            ulonglong2 v = wr[k];
            w2[2*k]   = v.x;
            w2[2*k+1] = v.y;
        }
    }

    if (j < NSEQ) {
        int sidx = (int)g_order[blockIdx.x * NSEQ + j];
        int off  = g_off[sidx];
        int end  = (sidx == B_SEQ - 1) ? T : g_off[sidx + 1];
        sh_meta[3*j]     = off;
        sh_meta[3*j + 1] = end - off;
        sh_meta[3*j + 2] = sidx;
    }
    if (j < 128) {
        #pragma unroll
        for (int s = 0; s < NSEQ; ++s) sh_h[s][j] = 0.f;
    }
    __syncthreads();

    int offs[NSEQ], lens[NSEQ];
    #pragma unroll
    for (int s = 0; s < NSEQ; ++s) {
        offs[s] = sh_meta[3*s];
        lens[s] = sh_meta[3*s + 1];
    }
    int maxlen = max(max(lens[0], lens[1]), max(lens[2], lens[3]));

    const float* xgp[NSEQ];
    float cur[NSEQ], nxt[NSEQ];
    #pragma unroll
    for (int s = 0; s < NSEQ; ++s) {
        xgp[s] = g_xproj + (size_t)offs[s] * G3 + j;
        cur[s] = xgp[s][0];
        nxt[s] = xgp[s][(size_t)min(1, lens[s] - 1) * G3];
    }

    // gate-phase role (loop-invariant): pass1 covers seqs 0-2, pass2 seq 3
    const int s1    = j >> 7;          // 0..2
    const int lane1 = j & 127;
    const int len_p1 = lens[s1];
    const bool p2   = (j < 128);
    const int len_p2 = lens[3];

    for (int t = 0; t < maxlen; ++t) {
        float pf[NSEQ];
        #pragma unroll
        for (int s = 0; s < NSEQ; ++s)
            pf[s] = xgp[s][(size_t)min(t + 2, lens[s] - 1) * G3];

        #pragma unroll
        for (int s = 0; s < NSEQ; ++s) {
            const ulonglong2* hv = reinterpret_cast<const ulonglong2*>(sh_h[s]);
            unsigned long long a0 = 0ull, a1 = 0ull, a2 = 0ull, a3 = 0ull;
            #pragma unroll
            for (int k = 0; k < 16; ++k) {
                ulonglong2 h0 = hv[2*k];
                ulonglong2 h1 = hv[2*k+1];
                ffma2(a0, w2[4*k+0], h0.x);
                ffma2(a1, w2[4*k+1], h0.y);
                ffma2(a2, w2[4*k+2], h1.x);
                ffma2(a3, w2[4*k+3], h1.y);
            }
            float hg = (unpack_sum(a0) + unpack_sum(a1)) +
                       (unpack_sum(a2) + unpack_sum(a3));
            sh_a[s][j] = cur[s] + hg;
            if (j >= 256) sh_hgn[s][j - 256] = hg;
        }
        __syncthreads();

        // gate pass 1: seqs 0-2, all 384 threads
        if (t < len_p1) {
            const float* a = sh_a[s1];
            float r = fast_sigmoid(a[lane1]);
            float z = fast_sigmoid(a[lane1 + 128]);
            float n = fast_tanh(a[lane1 + 256] + (r - 1.f) * sh_hgn[s1][lane1]);
            sh_h[s1][lane1] = (1.f - z) * n + z * sh_h[s1][lane1];
        }
        // gate pass 2: seq 3, threads 0-127
        if (p2 && t < len_p2) {
            const float* a = sh_a[3];
            float r = fast_sigmoid(a[j]);
            float z = fast_sigmoid(a[j + 128]);
            float n = fast_tanh(a[j + 256] + (r - 1.f) * sh_hgn[3][j]);
            sh_h[3][j] = (1.f - z) * n + z * sh_h[3][j];
        }
        __syncthreads();

        #pragma unroll
        for (int s = 0; s < NSEQ; ++s) { cur[s] = nxt[s]; nxt[s] = pf[s]; }
    }

    // ---- epilogue: dense + L2-normalize, 4 sequences ----
    float v1 = 0.f, v2 = 0.f;
    {
        const ulonglong2* wd =
            reinterpret_cast<const ulonglong2*>(W_dense + (size_t)lane1 * 128);
        const ulonglong2* hv = reinterpret_cast<const ulonglong2*>(sh_h[s1]);
        unsigned long long a0 = 0ull, a1 = 0ull;
        #pragma unroll
        for (int k = 0; k < 16; ++k) {
            ulonglong2 wv = wd[2*k];
            ulonglong2 wu = wd[2*k+1];
            ulonglong2 h0 = hv[2*k];
            ulonglong2 h1 = hv[2*k+1];
            ffma2(a0, wv.x, h0.x);
            ffma2(a1, wv.y, h0.y);
            ffma2(a0, wu.x, h1.x);
            ffma2(a1, wu.y, h1.y);
        }
        v1 = unpack_sum(a0) + unpack_sum(a1) + b_dense[lane1];
        float sq = v1 * v1;
        #pragma unroll
        for (int d = 16; d > 0; d >>= 1)
            sq += __shfl_xor_sync(0xffffffffu, sq, d);
        if ((lane1 & 31) == 0) sh_red[s1][lane1 >> 5] = sq;
    }
    if (p2) {
        const ulonglong2* wd =
            reinterpret_cast<const ulonglong2*>(W_dense + (size_t)j * 128);
        const ulonglong2* hv = reinterpret_cast<const ulonglong2*>(sh_h[3]);
        unsigned long long a0 = 0ull, a1 = 0ull;
        #pragma unroll
        for (int k = 0; k < 16; ++k) {
            ulonglong2 wv = wd[2*k];
            ulonglong2 wu = wd[2*k+1];
            ulonglong2 h0 = hv[2*k];
            ulonglong2 h1 = hv[2*k+1];
            ffma2(a0, wv.x, h0.x);
            ffma2(a1, wv.y, h0.y);
            ffma2(a0, wu.x, h1.x);
            ffma2(a1, wu.y, h1.y);
        }
        v2 = unpack_sum(a0) + unpack_sum(a1) + b_dense[j];
        float sq = v2 * v2;
        #pragma unroll
        for (int d = 16; d > 0; d >>= 1)
            sq += __shfl_xor_sync(0xffffffffu, sq, d);
        if ((j & 31) == 0) sh_red[3][j >> 5] = sq;
    }
    __syncthreads();
    if (j < NSEQ) {
        float ss = sh_red[j][0] + sh_red[j][1] + sh_red[j][2] + sh_red[j][3];
        sh_inv[j] = 1.f / fmaxf(sqrtf(ss), 1e-12f);
    }
    __syncthreads();
    {
        const int sidx = sh_meta[3*s1 + 2];
        out[(size_t)sidx * D_DIM + lane1] = v1 * sh_inv[s1];
    }
    if (p2) {
        const int sidx = sh_meta[3*3 + 2];
        out[(size_t)sidx * D_DIM + j] = v2 * sh_inv[3];
    }
}

// ---------------------------------------------------------------------------
extern "C" void kernel_launch(void* const* d_in, const int* in_sizes, int n_in,
                              void* d_out, int out_size) {
    const float* x       = (const float*)d_in[0];
    const void*  off_raw = d_in[1];
    const float* W_ih    = (const float*)d_in[2];
    const float* W_hh    = (const float*)d_in[3];
    const float* W_dense = (const float*)d_in[4];
    const float* b_dense = (const float*)d_in[5];
    float* out = (float*)d_out;

    const int T = in_sizes[0] / D_DIM;

    offsets_kernel<<<2, 1024>>>(off_raw);
    sort_kernel<<<1, 1024>>>(T);

    xproj_kernel<<<148, 384>>>(x, W_ih, T);

    gru_kernel<<<B_SEQ / NSEQ, 384>>>(W_hh, W_dense, b_dense, out, T);
}